// round 1
// baseline (speedup 1.0000x reference)
#include <cuda_runtime.h>

#define BB 8
#define C 256
#define HID 64
#define G 16
#define KK 9
#define GKK 144
#define HW 4096
#define IMG_W 64
#define IMG_H 64

// device scratch (allocation-free rule: __device__ globals)
__device__ __align__(16) float g_hid[BB * HID * HW];    // 8 MB
__device__ __align__(16) float g_kmap[BB * GKK * HW];   // 18 MB

// ---------------------------------------------------------------------------
// Kernel 1: hid[b,o,p] = relu(sum_c w_reduce[o,c] * x[b,c,p] + b_reduce[o])
// CTA: one batch, 128 pixels, all 64 outputs. 256 threads = 32 px-groups(4) x 8 out-groups(8).
// ---------------------------------------------------------------------------
__global__ __launch_bounds__(256) void k_reduce(const float* __restrict__ x,
                                                const float* __restrict__ wr,
                                                const float* __restrict__ br) {
    __shared__ __align__(16) float xs[32 * 128];  // xs[cc*128 + p]
    __shared__ __align__(16) float ws[64 * 32];   // ws[o*32 + cc]
    const int tid = threadIdx.x;
    const int b  = blockIdx.x >> 5;
    const int pt = (blockIdx.x & 31) << 7;   // pixel tile base
    const int pg = tid & 31;                 // pixel group (4 px)
    const int og = tid >> 5;                 // out group == warp id (8 outs)

    float acc[8][4];
#pragma unroll
    for (int i = 0; i < 8; i++)
#pragma unroll
        for (int j = 0; j < 4; j++) acc[i][j] = 0.f;

    for (int ck = 0; ck < 8; ck++) {
        // load x chunk: 32 channels x 128 px = 1024 float4
#pragma unroll
        for (int i = 0; i < 4; i++) {
            int lin = tid + i * 256;            // float4 index
            int cc = lin >> 5, p4 = lin & 31;
            float4 v = *(const float4*)(x + ((size_t)(b * C + ck * 32 + cc)) * HW + pt + p4 * 4);
            *(float4*)(xs + cc * 128 + p4 * 4) = v;
        }
        // load w chunk: 64 o x 32 cc
#pragma unroll
        for (int i = 0; i < 8; i++) {
            int lin = tid + i * 256;            // = o*32 + cc
            int o = lin >> 5, cc = lin & 31;
            ws[lin] = wr[o * C + ck * 32 + cc];
        }
        __syncthreads();
#pragma unroll
        for (int cc = 0; cc < 32; cc++) {
            float4 xv = *(const float4*)(xs + cc * 128 + pg * 4);
#pragma unroll
            for (int om = 0; om < 8; om++) {
                float wv = ws[(og * 8 + om) * 32 + cc];   // warp-uniform broadcast
                acc[om][0] = fmaf(wv, xv.x, acc[om][0]);
                acc[om][1] = fmaf(wv, xv.y, acc[om][1]);
                acc[om][2] = fmaf(wv, xv.z, acc[om][2]);
                acc[om][3] = fmaf(wv, xv.w, acc[om][3]);
            }
        }
        __syncthreads();
    }
#pragma unroll
    for (int om = 0; om < 8; om++) {
        int o = og * 8 + om;
        float bias = __ldg(br + o);
        float4 r;
        r.x = fmaxf(acc[om][0] + bias, 0.f);
        r.y = fmaxf(acc[om][1] + bias, 0.f);
        r.z = fmaxf(acc[om][2] + bias, 0.f);
        r.w = fmaxf(acc[om][3] + bias, 0.f);
        *(float4*)(g_hid + ((size_t)(b * HID + o)) * HW + pt + pg * 4) = r;
    }
}

// ---------------------------------------------------------------------------
// Kernel 2: Kmap[b,o,p] = sum_h w_span[o,h] * hid[b,h,p] + b_span[o]
// CTA: one batch, 128 px, all 144 outs. 288 threads = 32 px-groups(4) x 9 out-groups(16).
// ---------------------------------------------------------------------------
__global__ __launch_bounds__(288) void k_span(const float* __restrict__ wsp,
                                              const float* __restrict__ bs) {
    __shared__ __align__(16) float hs[32 * 128];   // hs[hh*128 + p]
    __shared__ __align__(16) float ws[144 * 32];   // ws[o*32 + hh]
    const int tid = threadIdx.x;
    const int b  = blockIdx.x >> 5;
    const int pt = (blockIdx.x & 31) << 7;
    const int pg = tid & 31;
    const int og = tid >> 5;                       // 0..8, == warp id

    float acc[16][4];
#pragma unroll
    for (int i = 0; i < 16; i++)
#pragma unroll
        for (int j = 0; j < 4; j++) acc[i][j] = 0.f;

    for (int hc = 0; hc < 2; hc++) {
        for (int idx = tid; idx < 32 * 128; idx += 288) {
            int hh = idx >> 7, p = idx & 127;
            hs[idx] = g_hid[((size_t)(b * HID + hc * 32 + hh)) * HW + pt + p];
        }
        for (int idx = tid; idx < 144 * 32; idx += 288) {
            int o = idx >> 5, hh = idx & 31;
            ws[idx] = wsp[o * HID + hc * 32 + hh];
        }
        __syncthreads();
#pragma unroll
        for (int hh = 0; hh < 32; hh++) {
            float4 xv = *(const float4*)(hs + hh * 128 + pg * 4);
#pragma unroll
            for (int om = 0; om < 16; om++) {
                float wv = ws[(og * 16 + om) * 32 + hh];  // warp-uniform broadcast
                acc[om][0] = fmaf(wv, xv.x, acc[om][0]);
                acc[om][1] = fmaf(wv, xv.y, acc[om][1]);
                acc[om][2] = fmaf(wv, xv.z, acc[om][2]);
                acc[om][3] = fmaf(wv, xv.w, acc[om][3]);
            }
        }
        __syncthreads();
    }
#pragma unroll
    for (int om = 0; om < 16; om++) {
        int o = og * 16 + om;
        float bias = __ldg(bs + o);
        float4 r;
        r.x = acc[om][0] + bias;
        r.y = acc[om][1] + bias;
        r.z = acc[om][2] + bias;
        r.w = acc[om][3] + bias;
        *(float4*)(g_kmap + ((size_t)(b * GKK + o)) * HW + pt + pg * 4) = r;
    }
}

// ---------------------------------------------------------------------------
// Kernel 3: involution. out[b, g*16+ch, y, x] =
//   sum_{dy,dx} x[b, g*16+ch, y+dy-1, x+dx-1] * Kmap[b, g*9 + dy*3+dx, y, x]
// CTA: (tile16x16, g, b). 256 threads = one per pixel; each does 16 channels,
// Kmap's 9 values held in registers across the channel loop.
// ---------------------------------------------------------------------------
__global__ __launch_bounds__(256) void k_invol(const float* __restrict__ x,
                                               float* __restrict__ out) {
    __shared__ __align__(16) float xs[16 * 18 * 20];  // [ch][row(18)][col stride 20]
    const int tid = threadIdx.x;
    const int tile = blockIdx.x;              // 0..15
    const int g = blockIdx.y;
    const int b = blockIdx.z;
    const int ty = (tile >> 2) * 16;
    const int tx = (tile & 3) * 16;

    // cooperative load of 16ch x 18x18 halo tile (zero padded at borders)
    for (int idx = tid; idx < 16 * 18 * 18; idx += 256) {
        int ch  = idx / 324;
        int rem = idx - ch * 324;
        int r  = rem / 18;
        int cc = rem - r * 18;
        int Y = ty + r - 1, X = tx + cc - 1;
        float v = 0.f;
        if (Y >= 0 && Y < IMG_H && X >= 0 && X < IMG_W)
            v = x[((size_t)(b * C + g * 16 + ch)) * HW + Y * IMG_W + X];
        xs[ch * 360 + r * 20 + cc] = v;
    }
    __syncthreads();

    const int px = tid & 15, py = tid >> 4;
    const int Y = ty + py, X = tx + px;

    float km[9];
#pragma unroll
    for (int k = 0; k < 9; k++)
        km[k] = g_kmap[(((size_t)(b * G + g)) * KK + k) * HW + Y * IMG_W + X];

#pragma unroll 4
    for (int ch = 0; ch < 16; ch++) {
        float s = 0.f;
#pragma unroll
        for (int dy = 0; dy < 3; dy++)
#pragma unroll
            for (int dx = 0; dx < 3; dx++)
                s = fmaf(xs[ch * 360 + (py + dy) * 20 + (px + dx)], km[dy * 3 + dx], s);
        out[((size_t)(b * C + g * 16 + ch)) * HW + Y * IMG_W + X] = s;
    }
}

// ---------------------------------------------------------------------------
extern "C" void kernel_launch(void* const* d_in, const int* in_sizes, int n_in,
                              void* d_out, int out_size) {
    const float* x   = (const float*)d_in[0];
    const float* wr  = (const float*)d_in[1];
    const float* br  = (const float*)d_in[2];
    const float* wsp = (const float*)d_in[3];
    const float* bs  = (const float*)d_in[4];
    float* out = (float*)d_out;

    k_reduce<<<BB * (HW / 128), 256>>>(x, wr, br);
    k_span<<<BB * (HW / 128), 288>>>(wsp, bs);
    dim3 g3(16, G, BB);
    k_invol<<<g3, 256>>>(x, out);
}